// round 6
// baseline (speedup 1.0000x reference)
#include <cuda_runtime.h>
#include <math.h>

// Problem constants (match reference)
#define Wd 96
#define Hd 96
#define Dd 64
#define Ad 90
#define Ud 96
#define Vd 64
#define NSTEPS 194          // H + W + 2
#define NRAYS  (Ad * Ud)    // 8640
#define WPB    4            // warps per block in accumulate kernel (2 rays/warp)

// Static device scratch (no allocations allowed).
// Packed trace: .x = voxel base offset (i*H*D + j*D), .y = weight bits.
__device__ int2 g_trace[NRAYS * NSTEPS];
__device__ int  g_cnt[NRAYS];

__device__ __forceinline__ void t_for(float p0, float dp, float pmin, float pmax,
                                      float& lo, float& hi) {
    const float EPS = 1e-12f;
    bool par = fabsf(dp) < EPS;
    float safe = par ? 1.0f : dp;
    float t0 = (pmin - p0) / safe;
    float t1 = (pmax - p0) / safe;
    lo = fminf(t0, t1);
    hi = fmaxf(t0, t1);
    bool inside = (p0 >= pmin) && (p0 <= pmax);
    if (par) {
        lo = inside ? -INFINITY : INFINITY;
        hi = inside ?  INFINITY : -INFINITY;
    }
}

// One thread per ray, incremental Siddon: absolute next-crossing times TX/TY
// advanced by constant increments -> short loop-carried dependency chain.
__global__ __launch_bounds__(64) void siddon_trace_kernel() {
    int r = blockIdx.x * blockDim.x + threadIdx.x;
    if (r >= NRAYS) return;

    const float EPS  = 1e-12f;
    const float DIAG = 1.41421356237309515f;  // f32(sqrt(2))

    int a  = r / Ud;
    int ui = r % Ud;

    const float ang_step = 3.14159274101257324f / 90.0f;
    float ang = (float)a * ang_step;
    float ct = (float)cos((double)ang);
    float st = (float)sin((double)ang);

    float u  = (float)ui - 47.5f;
    float dx = ct, dy = st;
    float x0 = -u * st;
    float y0 =  u * ct;

    const float pmin = -47.5f, pmax = 47.5f;

    float tx0, tx1, ty0, ty1;
    t_for(x0, dx, pmin, pmax, tx0, tx1);
    t_for(y0, dy, pmin, pmax, ty0, ty1);

    float t_entry = fmaxf(tx0, ty0);
    float t_exit  = fminf(tx1, ty1);
    bool  alive   = t_entry < t_exit;
    float te  = alive ? t_entry : 0.0f;
    float tex = alive ? t_exit  : 0.0f;

    float xe = x0 + te * dx;
    float ye = y0 + te * dy;

    int i = (int)fminf(fmaxf(rintf(xe + 47.5f), 0.0f), (float)(Wd - 1));
    int j = (int)fminf(fmaxf(rintf(ye + 47.5f), 0.0f), (float)(Hd - 1));

    float wscale = DIAG / fmaxf(fabsf(dx) + fabsf(dy), EPS);

    bool okx = fabsf(dx) > EPS;
    bool oky = fabsf(dy) > EPS;
    float inv_dx = okx ? (1.0f / dx) : 0.0f;
    float inv_dy = oky ? (1.0f / dy) : 0.0f;

    float xoff = (dx > 0.0f) ? (0.5f - 47.5f) : (-0.5f - 47.5f);
    float yoff = (dy > 0.0f) ? (0.5f - 47.5f) : (-0.5f - 47.5f);
    int   istep = (dx > 0.0f) ? 1 : -1;
    int   jstep = (dy > 0.0f) ? 1 : -1;

    // Absolute times of next x/y plane crossings, and per-crossing increments.
    float TX = okx ? (te + (((float)i + xoff) - xe) * inv_dx) : INFINITY;
    float TY = oky ? (te + (((float)j + yoff) - ye) * inv_dy) : INFINITY;
    float dtx = okx ? fabsf(inv_dx) : 0.0f;
    float dty = oky ? fabsf(inv_dy) : 0.0f;

    float t = te;
    int cnt  = 0;
    int base = r * NSTEPS;

    for (int s = 0; s < NSTEPS && alive; s++) {
        bool valid = (t < tex - EPS);

        float tm   = fminf(TX, TY);
        float tend = fminf(tm, tex);
        float dt   = tend - t;
        float w    = fmaxf(0.0f, dt * wscale);

        if (valid && w > 0.0f) {
            int2 e;
            e.x = i * (Hd * Dd) + j * Dd;
            e.y = __float_as_int(w);
            g_trace[base + cnt] = e;
            cnt++;
        }

        bool cx = (TX <= TY);
        bool cy = (TY <= TX);
        int i_n = i + (cx ? istep : 0);
        int j_n = j + (cy ? jstep : 0);
        bool inb = (i_n >= 0) && (i_n < Wd) && (j_n >= 0) && (j_n < Hd);

        if (valid) {
            i = i_n; j = j_n; t = tend;
            if (cx) TX += dtx;
            if (cy) TY += dty;
        }
        alive = valid && inb;
    }
    g_cnt[r] = cnt;
}

// Block = WPB warps; each warp handles 2 rays: lanes 0-15 -> ray A, 16-31 -> ray B.
// Each lane loads float4 (4 v-values); unroll 4 for MLP.
__global__ __launch_bounds__(32 * WPB) void siddon_accum_kernel(
        const float* __restrict__ vol, float* __restrict__ out) {
    __shared__ int2 s_t[WPB][2][NSTEPS];

    int tid = threadIdx.x;
    int wr  = tid >> 5;          // warp in block
    int l   = tid & 31;          // lane
    int h   = l >> 4;            // half-warp -> which ray
    int vi  = l & 15;            // float4 index: v = 4*vi .. 4*vi+3

    int ray  = (blockIdx.x * WPB + wr) * 2 + h;
    int cnt  = g_cnt[ray];
    int base = ray * NSTEPS;

    for (int n = vi; n < cnt; n += 16)
        s_t[wr][h][n] = g_trace[base + n];
    __syncwarp();

    const float4* vp4 = (const float4*)vol;

    float4 a0 = make_float4(0.f, 0.f, 0.f, 0.f);
    float4 a1 = make_float4(0.f, 0.f, 0.f, 0.f);
    float4 a2 = make_float4(0.f, 0.f, 0.f, 0.f);
    float4 a3 = make_float4(0.f, 0.f, 0.f, 0.f);

    int n = 0;
    for (; n + 3 < cnt; n += 4) {
        int2 e0 = s_t[wr][h][n + 0];
        int2 e1 = s_t[wr][h][n + 1];
        int2 e2 = s_t[wr][h][n + 2];
        int2 e3 = s_t[wr][h][n + 3];
        float4 v0 = vp4[(e0.x >> 2) + vi];
        float4 v1 = vp4[(e1.x >> 2) + vi];
        float4 v2 = vp4[(e2.x >> 2) + vi];
        float4 v3 = vp4[(e3.x >> 2) + vi];
        float w0 = __int_as_float(e0.y);
        float w1 = __int_as_float(e1.y);
        float w2 = __int_as_float(e2.y);
        float w3 = __int_as_float(e3.y);
        a0.x += v0.x * w0; a0.y += v0.y * w0; a0.z += v0.z * w0; a0.w += v0.w * w0;
        a1.x += v1.x * w1; a1.y += v1.y * w1; a1.z += v1.z * w1; a1.w += v1.w * w1;
        a2.x += v2.x * w2; a2.y += v2.y * w2; a2.z += v2.z * w2; a2.w += v2.w * w2;
        a3.x += v3.x * w3; a3.y += v3.y * w3; a3.z += v3.z * w3; a3.w += v3.w * w3;
    }
    for (; n < cnt; n++) {
        int2 e = s_t[wr][h][n];
        float4 v = vp4[(e.x >> 2) + vi];
        float w = __int_as_float(e.y);
        a0.x += v.x * w; a0.y += v.y * w; a0.z += v.z * w; a0.w += v.w * w;
    }

    float4 res;
    res.x = (a0.x + a1.x) + (a2.x + a3.x);
    res.y = (a0.y + a1.y) + (a2.y + a3.y);
    res.z = (a0.z + a1.z) + (a2.z + a3.z);
    res.w = (a0.w + a1.w) + (a2.w + a3.w);

    int a  = ray / Ud;
    int ui = ray % Ud;
    // output layout (B,C,U,A,V): float4 index = ((u*A + a)*V)/4 + vi
    ((float4*)out)[((ui * Ad + a) * Vd >> 2) + vi] = res;
}

extern "C" void kernel_launch(void* const* d_in, const int* in_sizes, int n_in,
                              void* d_out, int out_size) {
    const float* vol = (const float*)d_in[0];
    float* out = (float*)d_out;

    siddon_trace_kernel<<<(NRAYS + 63) / 64, 64>>>();

    dim3 blk(32 * WPB);                    // 128 threads
    dim3 grd(NRAYS / (2 * WPB));           // 1080 blocks
    siddon_accum_kernel<<<grd, blk>>>(vol, out);
}